// round 1
// baseline (speedup 1.0000x reference)
#include <cuda_runtime.h>
#include <cuda_bf16.h>
#include <math_constants.h>

// Shapes (fixed by the problem)
#define BB 8
#define LL 1024
#define HH 512
#define FF 4
#define HF 2048      // H*F
#define H2 1024      // 2*H
#define MROWS 8192   // B*L

// Scratch (device globals — no allocation allowed)
__device__ float g_yt[(size_t)BB * FF * LL * HH];   // (B,F,L,H) transposed relu(proj)
__device__ float g_S[(size_t)BB * LL * LL];         // scores -> alpha (in place)
__device__ float g_joint[(size_t)BB * LL * H2];     // [x, enc]

// ---------------- Tiled SGEMM skeleton: 64x64 tile, BK=16, 16x16 threads, 4x4/thread --------
#define BM 64
#define BN 64
#define BK 16
#define SPAD 68  // 64 + 4 pad (keeps float4 alignment, breaks worst bank conflicts)

// ---------------------------------------------------------------------------
// K1: Y = relu(X @ W_proj + b_proj), scatter to yt[(b,f,l,h)]
// M=8192, N=2048, K=512
// ---------------------------------------------------------------------------
__global__ void k_proj(const float* __restrict__ X, const float* __restrict__ W,
                       const float* __restrict__ bias) {
    __shared__ float As[BK][SPAD];
    __shared__ float Bs[BK][SPAD];
    const int tx = threadIdx.x, ty = threadIdx.y;
    const int tid = ty * 16 + tx;
    const int m0 = blockIdx.y * BM;
    const int n0 = blockIdx.x * BN;

    const int arow  = tid >> 2;          // 0..63
    const int acol4 = (tid & 3) * 4;     // 0,4,8,12
    const int brow  = tid >> 4;          // 0..15
    const int bcol4 = (tid & 15) * 4;    // 0..60

    float acc[4][4] = {};
    for (int k0 = 0; k0 < HH; k0 += BK) {
        float4 av = *(const float4*)&X[(size_t)(m0 + arow) * HH + k0 + acol4];
        As[acol4 + 0][arow] = av.x;
        As[acol4 + 1][arow] = av.y;
        As[acol4 + 2][arow] = av.z;
        As[acol4 + 3][arow] = av.w;
        *(float4*)&Bs[brow][bcol4] = *(const float4*)&W[(size_t)(k0 + brow) * HF + n0 + bcol4];
        __syncthreads();
#pragma unroll
        for (int k = 0; k < BK; ++k) {
            float4 a = *(float4*)&As[k][ty * 4];
            float4 b = *(float4*)&Bs[k][tx * 4];
            float ar[4] = {a.x, a.y, a.z, a.w};
            float br[4] = {b.x, b.y, b.z, b.w};
#pragma unroll
            for (int i = 0; i < 4; ++i)
#pragma unroll
                for (int j = 0; j < 4; ++j) acc[i][j] = fmaf(ar[i], br[j], acc[i][j]);
        }
        __syncthreads();
    }
#pragma unroll
    for (int i = 0; i < 4; ++i) {
        int m = m0 + ty * 4 + i;
        int b = m >> 10, l = m & 1023;
#pragma unroll
        for (int j = 0; j < 4; ++j) {
            int n = n0 + tx * 4 + j;
            float v = acc[i][j] + bias[n];
            v = v > 0.f ? v : 0.f;
            int h = n >> 2, f = n & 3;
            g_yt[(((size_t)b * FF + f) * LL + l) * HH + h] = v;
        }
    }
}

// ---------------------------------------------------------------------------
// K2: S[b,l,m] = max_f  Yf[l,:] . Yf[m,:]   (NT GEMM per (b,f), running max)
// per batch: M=N=1024, K=512, f-loop inside block
// ---------------------------------------------------------------------------
__global__ void k_scores() {
    __shared__ float As[BK][SPAD];
    __shared__ float Bs[BK][SPAD];
    const int tx = threadIdx.x, ty = threadIdx.y;
    const int tid = ty * 16 + tx;
    const int b  = blockIdx.z;
    const int m0 = blockIdx.y * BM;
    const int n0 = blockIdx.x * BN;

    const int arow  = tid >> 2;
    const int acol4 = (tid & 3) * 4;

    float best[4][4];
#pragma unroll
    for (int i = 0; i < 4; ++i)
#pragma unroll
        for (int j = 0; j < 4; ++j) best[i][j] = -CUDART_INF_F;

    for (int f = 0; f < FF; ++f) {
        const float* Yf = g_yt + ((size_t)b * FF + f) * LL * HH;
        float acc[4][4] = {};
        for (int k0 = 0; k0 < HH; k0 += BK) {
            float4 av = *(const float4*)&Yf[(size_t)(m0 + arow) * HH + k0 + acol4];
            As[acol4 + 0][arow] = av.x;
            As[acol4 + 1][arow] = av.y;
            As[acol4 + 2][arow] = av.z;
            As[acol4 + 3][arow] = av.w;
            float4 bv = *(const float4*)&Yf[(size_t)(n0 + arow) * HH + k0 + acol4];
            Bs[acol4 + 0][arow] = bv.x;
            Bs[acol4 + 1][arow] = bv.y;
            Bs[acol4 + 2][arow] = bv.z;
            Bs[acol4 + 3][arow] = bv.w;
            __syncthreads();
#pragma unroll
            for (int k = 0; k < BK; ++k) {
                float4 a = *(float4*)&As[k][ty * 4];
                float4 bq = *(float4*)&Bs[k][tx * 4];
                float ar[4] = {a.x, a.y, a.z, a.w};
                float br[4] = {bq.x, bq.y, bq.z, bq.w};
#pragma unroll
                for (int i = 0; i < 4; ++i)
#pragma unroll
                    for (int j = 0; j < 4; ++j) acc[i][j] = fmaf(ar[i], br[j], acc[i][j]);
            }
            __syncthreads();
        }
#pragma unroll
        for (int i = 0; i < 4; ++i)
#pragma unroll
            for (int j = 0; j < 4; ++j) best[i][j] = fmaxf(best[i][j], acc[i][j]);
    }
#pragma unroll
    for (int i = 0; i < 4; ++i) {
        int m = m0 + ty * 4 + i;
#pragma unroll
        for (int j = 0; j < 4; ++j) {
            int n = n0 + tx * 4 + j;
            g_S[((size_t)b * LL + m) * LL + n] = best[i][j];
        }
    }
}

// ---------------------------------------------------------------------------
// K3: masked softmax (exact reference algebra), in place on g_S
// alpha = e*mask / (sum(e*mask) + 1e-13 * Z), e = exp(logits*mask - max)
// ---------------------------------------------------------------------------
__global__ void k_softmax(const int* __restrict__ xmask) {
    const int row = blockIdx.x;           // b*L + l
    const int b = row >> 10, l = row & 1023;
    const int t = threadIdx.x;            // 256 threads
    const int* xb = xmask + b * LL;
    float* Srow = g_S + (size_t)row * LL;
    const int ml = xb[l];

    float lm[4], msk[4];
    float mx = -CUDART_INF_F;
#pragma unroll
    for (int j = 0; j < 4; ++j) {
        int m = t + j * 256;
        float mk = (float)(ml * xb[m] * (m != l));
        float v = Srow[m] * mk;
        lm[j] = v; msk[j] = mk;
        mx = fmaxf(mx, v);
    }
    __shared__ float sh[256];
    sh[t] = mx; __syncthreads();
    for (int s = 128; s > 0; s >>= 1) {
        if (t < s) sh[t] = fmaxf(sh[t], sh[t + s]);
        __syncthreads();
    }
    const float rowmax = sh[0];
    __syncthreads();

    float e[4];
    float z = 0.f, sm = 0.f;
#pragma unroll
    for (int j = 0; j < 4; ++j) {
        e[j] = expf(lm[j] - rowmax);
        z += e[j];
        sm += e[j] * msk[j];
    }
    sh[t] = z; __syncthreads();
    for (int s = 128; s > 0; s >>= 1) {
        if (t < s) sh[t] += sh[t + s];
        __syncthreads();
    }
    const float Z = sh[0];
    __syncthreads();
    sh[t] = sm; __syncthreads();
    for (int s = 128; s > 0; s >>= 1) {
        if (t < s) sh[t] += sh[t + s];
        __syncthreads();
    }
    const float SM = sh[0];

    const float inv = 1.0f / (SM + 1e-13f * Z);
#pragma unroll
    for (int j = 0; j < 4; ++j) {
        int m = t + j * 256;
        Srow[m] = e[j] * msk[j] * inv;
    }
}

// ---------------------------------------------------------------------------
// K_copy: joint[:, 0:H] = x
// ---------------------------------------------------------------------------
__global__ void k_copyx(const float* __restrict__ X) {
    size_t total = (size_t)MROWS * HH / 4;  // float4 count
    for (size_t i = blockIdx.x * blockDim.x + threadIdx.x; i < total;
         i += (size_t)gridDim.x * blockDim.x) {
        size_t row = i / (HH / 4);
        size_t c4  = i % (HH / 4);
        float4 v = ((const float4*)X)[i];
        *(float4*)&g_joint[row * H2 + c4 * 4] = v;
    }
}

// ---------------------------------------------------------------------------
// K4: enc = alpha @ x_b, write to joint[:, H:2H].  per batch M=1024,N=512,K=1024
// ---------------------------------------------------------------------------
__global__ void k_enc(const float* __restrict__ X) {
    __shared__ float As[BK][SPAD];
    __shared__ float Bs[BK][SPAD];
    const int tx = threadIdx.x, ty = threadIdx.y;
    const int tid = ty * 16 + tx;
    const int b  = blockIdx.z;
    const int m0 = blockIdx.y * BM;
    const int n0 = blockIdx.x * BN;
    const float* A = g_S + (size_t)b * LL * LL;     // alpha (1024x1024)
    const float* Bx = X + (size_t)b * LL * HH;      // x_b   (1024x512)

    const int arow  = tid >> 2;
    const int acol4 = (tid & 3) * 4;
    const int brow  = tid >> 4;
    const int bcol4 = (tid & 15) * 4;

    float acc[4][4] = {};
    for (int k0 = 0; k0 < LL; k0 += BK) {
        float4 av = *(const float4*)&A[(size_t)(m0 + arow) * LL + k0 + acol4];
        As[acol4 + 0][arow] = av.x;
        As[acol4 + 1][arow] = av.y;
        As[acol4 + 2][arow] = av.z;
        As[acol4 + 3][arow] = av.w;
        *(float4*)&Bs[brow][bcol4] = *(const float4*)&Bx[(size_t)(k0 + brow) * HH + n0 + bcol4];
        __syncthreads();
#pragma unroll
        for (int k = 0; k < BK; ++k) {
            float4 a = *(float4*)&As[k][ty * 4];
            float4 bq = *(float4*)&Bs[k][tx * 4];
            float ar[4] = {a.x, a.y, a.z, a.w};
            float br[4] = {bq.x, bq.y, bq.z, bq.w};
#pragma unroll
            for (int i = 0; i < 4; ++i)
#pragma unroll
                for (int j = 0; j < 4; ++j) acc[i][j] = fmaf(ar[i], br[j], acc[i][j]);
        }
        __syncthreads();
    }
#pragma unroll
    for (int i = 0; i < 4; ++i) {
        int m = m0 + ty * 4 + i;
#pragma unroll
        for (int j = 0; j < 4; ++j) {
            int n = n0 + tx * 4 + j;
            g_joint[((size_t)b * LL + m) * H2 + HH + n] = acc[i][j];
        }
    }
}

// ---------------------------------------------------------------------------
// K5: out = sigmoid(joint @ W_gate + b_gate) * joint.  M=8192,N=1024,K=1024
// ---------------------------------------------------------------------------
__global__ void k_gate(const float* __restrict__ Wg, const float* __restrict__ bg,
                       float* __restrict__ out) {
    __shared__ float As[BK][SPAD];
    __shared__ float Bs[BK][SPAD];
    const int tx = threadIdx.x, ty = threadIdx.y;
    const int tid = ty * 16 + tx;
    const int m0 = blockIdx.y * BM;
    const int n0 = blockIdx.x * BN;

    const int arow  = tid >> 2;
    const int acol4 = (tid & 3) * 4;
    const int brow  = tid >> 4;
    const int bcol4 = (tid & 15) * 4;

    float acc[4][4] = {};
    for (int k0 = 0; k0 < H2; k0 += BK) {
        float4 av = *(const float4*)&g_joint[(size_t)(m0 + arow) * H2 + k0 + acol4];
        As[acol4 + 0][arow] = av.x;
        As[acol4 + 1][arow] = av.y;
        As[acol4 + 2][arow] = av.z;
        As[acol4 + 3][arow] = av.w;
        *(float4*)&Bs[brow][bcol4] = *(const float4*)&Wg[(size_t)(k0 + brow) * H2 + n0 + bcol4];
        __syncthreads();
#pragma unroll
        for (int k = 0; k < BK; ++k) {
            float4 a = *(float4*)&As[k][ty * 4];
            float4 bq = *(float4*)&Bs[k][tx * 4];
            float ar[4] = {a.x, a.y, a.z, a.w};
            float br[4] = {bq.x, bq.y, bq.z, bq.w};
#pragma unroll
            for (int i = 0; i < 4; ++i)
#pragma unroll
                for (int j = 0; j < 4; ++j) acc[i][j] = fmaf(ar[i], br[j], acc[i][j]);
        }
        __syncthreads();
    }
#pragma unroll
    for (int i = 0; i < 4; ++i) {
        int m = m0 + ty * 4 + i;
#pragma unroll
        for (int j = 0; j < 4; ++j) {
            int n = n0 + tx * 4 + j;
            float g = acc[i][j] + bg[n];
            g = 1.0f / (1.0f + expf(-g));
            float jv = g_joint[(size_t)m * H2 + n];
            out[(size_t)m * H2 + n] = g * jv;
        }
    }
}

extern "C" void kernel_launch(void* const* d_in, const int* in_sizes, int n_in,
                              void* d_out, int out_size) {
    const float* x  = (const float*)d_in[0];
    const int*   xm = (const int*)d_in[1];
    const float* Wp = (const float*)d_in[2];
    const float* bp = (const float*)d_in[3];
    const float* Wg = (const float*)d_in[4];
    const float* bg = (const float*)d_in[5];
    float* out = (float*)d_out;

    dim3 thr(16, 16);
    k_proj   <<<dim3(HF / BN, MROWS / BM), thr>>>(x, Wp, bp);
    k_scores <<<dim3(LL / BN, LL / BM, BB), thr>>>();
    k_softmax<<<MROWS, 256>>>(xm);
    k_copyx  <<<2048, 256>>>(x);
    k_enc    <<<dim3(HH / BN, LL / BM, BB), thr>>>(x);
    k_gate   <<<dim3(H2 / BN, MROWS / BM), thr>>>(Wg, bg, out);
}

// round 2
// speedup vs baseline: 2.4263x; 2.4263x over previous
#include <cuda_runtime.h>
#include <cuda_bf16.h>
#include <math_constants.h>

// Shapes (fixed)
#define BB 8
#define LL 1024
#define HH 512
#define FF 4
#define HF 2048
#define H2 1024
#define MROWS 8192

// ---------------- scratch (device globals, 16B-aligned for vector/TMA-ish access) ----
__device__ __align__(256) float g_S[(size_t)BB * LL * LL];        // scores fp32
__device__ __align__(256) float g_joint[(size_t)MROWS * H2];      // [x, enc] fp32
__device__ __align__(256) __nv_bfloat16 g_jh[(size_t)MROWS * H2]; // joint hi
__device__ __align__(256) __nv_bfloat16 g_jl[(size_t)MROWS * H2]; // joint lo
__device__ __align__(256) __nv_bfloat16 g_xth[(size_t)BB * HH * LL]; // x^T per batch hi
__device__ __align__(256) __nv_bfloat16 g_xtl[(size_t)BB * HH * LL];
__device__ __align__(256) __nv_bfloat16 g_wph[(size_t)HF * HH];   // Wproj^T (f-major reindexed) hi
__device__ __align__(256) __nv_bfloat16 g_wpl[(size_t)HF * HH];
__device__ __align__(256) float g_bpr[HF];                        // reindexed proj bias
__device__ __align__(256) __nv_bfloat16 g_wgh[(size_t)H2 * H2];   // Wgate^T hi
__device__ __align__(256) __nv_bfloat16 g_wgl[(size_t)H2 * H2];
__device__ __align__(256) __nv_bfloat16 g_yh[(size_t)BB * FF * LL * HH]; // relu proj hi
__device__ __align__(256) __nv_bfloat16 g_yl[(size_t)BB * FF * LL * HH];
__device__ __align__(256) __nv_bfloat16 g_ah[(size_t)BB * LL * LL];      // alpha hi
__device__ __align__(256) __nv_bfloat16 g_al[(size_t)BB * LL * LL];

// ---------------- helpers --------------------------------------------------
__device__ __forceinline__ void split2(float v, __nv_bfloat16& h, __nv_bfloat16& l) {
    h = __float2bfloat16_rn(v);
    l = __float2bfloat16_rn(v - __bfloat162float(h));
}

__device__ __forceinline__ void cp16(void* smem, const void* gmem) {
    unsigned s = (unsigned)__cvta_generic_to_shared(smem);
    asm volatile("cp.async.cg.shared.global [%0], [%1], 16;\n" :: "r"(s), "l"(gmem));
}
__device__ __forceinline__ void cp_commit() { asm volatile("cp.async.commit_group;\n"); }
__device__ __forceinline__ void cp_wait0()  { asm volatile("cp.async.wait_group 0;\n"); }

__device__ __forceinline__ void ldsm4(unsigned& r0, unsigned& r1, unsigned& r2, unsigned& r3,
                                      const void* p) {
    unsigned s = (unsigned)__cvta_generic_to_shared(p);
    asm volatile("ldmatrix.sync.aligned.m8n8.x4.shared.b16 {%0,%1,%2,%3}, [%4];\n"
                 : "=r"(r0), "=r"(r1), "=r"(r2), "=r"(r3) : "r"(s));
}

__device__ __forceinline__ void mma16816(float* c, const unsigned* a, const unsigned* b) {
    asm volatile(
        "mma.sync.aligned.m16n8k16.row.col.f32.bf16.bf16.f32 "
        "{%0,%1,%2,%3}, {%4,%5,%6,%7}, {%8,%9}, {%0,%1,%2,%3};\n"
        : "+f"(c[0]), "+f"(c[1]), "+f"(c[2]), "+f"(c[3])
        : "r"(a[0]), "r"(a[1]), "r"(a[2]), "r"(a[3]), "r"(b[0]), "r"(b[1]));
}

// ---------------- mma GEMM template core -----------------------------------
// Block tile 128x128, K-tile 32 (bf16), 256 threads (8 warps, 2m x 4n),
// warp tile 64x32 (4 m16 tiles x 4 n8 tiles). NT: A [M,K] row-major, B [N,K] row-major.
#define BM 128
#define BN 128
#define BKE 32
#define SSTR 40  // smem row stride in bf16 (80B: conflict-free ldmatrix phases)
#define SBUF (128 * SSTR)

__device__ __forceinline__ void load_tile(__nv_bfloat16* sA, __nv_bfloat16* sB,
                                          const __nv_bfloat16* A, int lda,
                                          const __nv_bfloat16* B, int ldb,
                                          int m0, int n0, int kk, int tid) {
#pragma unroll
    for (int i = 0; i < 2; ++i) {
        int idx = tid + i * 256;
        int row = idx >> 2, seg = (idx & 3) * 8;
        cp16(&sA[row * SSTR + seg], &A[(size_t)(m0 + row) * lda + kk + seg]);
    }
#pragma unroll
    for (int i = 0; i < 2; ++i) {
        int idx = tid + i * 256;
        int row = idx >> 2, seg = (idx & 3) * 8;
        cp16(&sB[row * SSTR + seg], &B[(size_t)(n0 + row) * ldb + kk + seg]);
    }
    cp_commit();
}

__device__ __forceinline__ void compute_tile(float (&acc)[4][4][4],
                                             const __nv_bfloat16* sA,
                                             const __nv_bfloat16* sB,
                                             int wm, int wn, int lane) {
#pragma unroll
    for (int ks = 0; ks < 2; ++ks) {
        const int col = ks * 16 + (lane >> 4) * 8;
        unsigned af[4][4];
        unsigned bf[4][2];
#pragma unroll
        for (int mt = 0; mt < 4; ++mt) {
            int row = wm * 64 + mt * 16 + (lane & 15);
            ldsm4(af[mt][0], af[mt][1], af[mt][2], af[mt][3], &sA[row * SSTR + col]);
        }
#pragma unroll
        for (int np = 0; np < 2; ++np) {
            int row = wn * 32 + np * 16 + (lane & 15);
            unsigned r0, r1, r2, r3;
            ldsm4(r0, r1, r2, r3, &sB[row * SSTR + col]);
            bf[np * 2 + 0][0] = r0; bf[np * 2 + 1][0] = r1;
            bf[np * 2 + 0][1] = r2; bf[np * 2 + 1][1] = r3;
        }
#pragma unroll
        for (int mt = 0; mt < 4; ++mt)
#pragma unroll
            for (int nt = 0; nt < 4; ++nt)
                mma16816(acc[mt][nt], af[mt], bf[nt]);
    }
}

// 3-pass split-bf16 mainloop: acc += Ah*Bh^T + Ah*Bl^T + Al*Bh^T
__device__ __forceinline__ void gemm_main(float (&acc)[4][4][4],
                                          const __nv_bfloat16* Ah, const __nv_bfloat16* Al, int lda,
                                          const __nv_bfloat16* Bh, const __nv_bfloat16* Bl, int ldb,
                                          int K, int m0, int n0,
                                          __nv_bfloat16* sA0, __nv_bfloat16* sB0,
                                          __nv_bfloat16* sA1, __nv_bfloat16* sB1) {
    const int tid = threadIdx.x;
    const int lane = tid & 31, warp = tid >> 5;
    const int wm = warp & 1, wn = warp >> 1;
    const int KT = K / BKE;
    const int total = 3 * KT;

    load_tile(sA0, sB0, Ah, lda, Bh, ldb, m0, n0, 0, tid);
    for (int s = 0; s < total; ++s) {
        cp_wait0();
        __syncthreads();
        if (s + 1 < total) {
            const int p = (s + 1) / KT;
            const int kk = ((s + 1) % KT) * BKE;
            const __nv_bfloat16* A = (p == 2) ? Al : Ah;
            const __nv_bfloat16* B = (p == 1) ? Bl : Bh;
            __nv_bfloat16* dA = ((s + 1) & 1) ? sA1 : sA0;
            __nv_bfloat16* dB = ((s + 1) & 1) ? sB1 : sB0;
            load_tile(dA, dB, A, lda, B, ldb, m0, n0, kk, tid);
        }
        const __nv_bfloat16* cA = (s & 1) ? sA1 : sA0;
        const __nv_bfloat16* cB = (s & 1) ? sB1 : sB0;
        compute_tile(acc, cA, cB, wm, wn, lane);
    }
}

#define GEMM_SMEM() \
    __shared__ __nv_bfloat16 smem[4 * SBUF]; \
    __nv_bfloat16* sA0 = smem; \
    __nv_bfloat16* sB0 = smem + SBUF; \
    __nv_bfloat16* sA1 = smem + 2 * SBUF; \
    __nv_bfloat16* sB1 = smem + 3 * SBUF;

// ---------------- prep kernels ---------------------------------------------
// x -> joint[:, :H] (fp32 + hi/lo) and per-batch transpose -> xt hi/lo
__global__ void k_prep_x(const float* __restrict__ X) {
    __shared__ float tile[32][33];
    const int b = blockIdx.z;
    const int l0 = blockIdx.y * 32, h0 = blockIdx.x * 32;
    const int tx = threadIdx.x, ty = threadIdx.y;
#pragma unroll
    for (int i = 0; i < 4; ++i) {
        int l = l0 + ty + 8 * i;
        float v = X[((size_t)b * LL + l) * HH + h0 + tx];
        tile[ty + 8 * i][tx] = v;
        size_t jo = ((size_t)b * LL + l) * H2 + h0 + tx;
        g_joint[jo] = v;
        __nv_bfloat16 hh, ll; split2(v, hh, ll);
        g_jh[jo] = hh; g_jl[jo] = ll;
    }
    __syncthreads();
#pragma unroll
    for (int i = 0; i < 4; ++i) {
        int h = h0 + ty + 8 * i;
        float v = tile[tx][ty + 8 * i];
        size_t o = ((size_t)b * HH + h) * LL + l0 + tx;
        __nv_bfloat16 hh, ll; split2(v, hh, ll);
        g_xth[o] = hh; g_xtl[o] = ll;
    }
}

// Wproj [H, HF] -> Wpt[n'][k], n' = f*512 + h  (n = h*4 + f); bias reindex
__global__ void k_prep_wp(const float* __restrict__ W, const float* __restrict__ bp) {
    __shared__ float tile[32][33];
    const int k0 = blockIdx.y * 32, n0 = blockIdx.x * 32;
    const int tx = threadIdx.x, ty = threadIdx.y;
#pragma unroll
    for (int i = 0; i < 4; ++i)
        tile[ty + 8 * i][tx] = W[(size_t)(k0 + ty + 8 * i) * HF + n0 + tx];
    __syncthreads();
#pragma unroll
    for (int i = 0; i < 4; ++i) {
        int n = n0 + ty + 8 * i;
        int np = ((n & 3) << 9) + (n >> 2);
        float v = tile[tx][ty + 8 * i];
        __nv_bfloat16 hh, ll; split2(v, hh, ll);
        size_t o = (size_t)np * HH + k0 + tx;
        g_wph[o] = hh; g_wpl[o] = ll;
        if (k0 == 0 && tx == 0) g_bpr[np] = bp[n];
    }
}

// Wgate [2H, 2H] -> Wgt[n][k]
__global__ void k_prep_wg(const float* __restrict__ W) {
    __shared__ float tile[32][33];
    const int k0 = blockIdx.y * 32, n0 = blockIdx.x * 32;
    const int tx = threadIdx.x, ty = threadIdx.y;
#pragma unroll
    for (int i = 0; i < 4; ++i)
        tile[ty + 8 * i][tx] = W[(size_t)(k0 + ty + 8 * i) * H2 + n0 + tx];
    __syncthreads();
#pragma unroll
    for (int i = 0; i < 4; ++i) {
        int n = n0 + ty + 8 * i;
        float v = tile[tx][ty + 8 * i];
        __nv_bfloat16 hh, ll; split2(v, hh, ll);
        size_t o = (size_t)n * H2 + k0 + tx;
        g_wgh[o] = hh; g_wgl[o] = ll;
    }
}

// ---------------- GEMM kernels ----------------------------------------------
// proj: y = relu(x @ Wp + bp) -> yt hi/lo (B,F,L,H).  M=8192, N=2048(f-major), K=512
__global__ __launch_bounds__(256) void k_gemm_proj() {
    GEMM_SMEM();
    float acc[4][4][4] = {};
    const int m0 = blockIdx.y * BM, n0 = blockIdx.x * BN;
    gemm_main(acc, g_jh, g_jl, H2, g_wph, g_wpl, HH, HH, m0, n0, sA0, sB0, sA1, sB1);

    const int lane = threadIdx.x & 31, warp = threadIdx.x >> 5;
    const int wm = warp & 1, wn = warp >> 1;
    const int r = lane >> 2, c = (lane & 3) * 2;
#pragma unroll
    for (int mt = 0; mt < 4; ++mt)
#pragma unroll
        for (int nt = 0; nt < 4; ++nt)
#pragma unroll
            for (int half = 0; half < 2; ++half) {
                int m = m0 + wm * 64 + mt * 16 + r + half * 8;
                int n = n0 + wn * 32 + nt * 8 + c;
                float2 bb = *(const float2*)&g_bpr[n];
                float v0 = fmaxf(acc[mt][nt][half * 2 + 0] + bb.x, 0.f);
                float v1 = fmaxf(acc[mt][nt][half * 2 + 1] + bb.y, 0.f);
                int b = m >> 10, l = m & 1023;
                int f = n >> 9, h = n & 511;
                size_t o = (((size_t)(b * FF + f)) * LL + l) * HH + h;
                __nv_bfloat16 h0, l0, h1, l1;
                split2(v0, h0, l0); split2(v1, h1, l1);
                __nv_bfloat162 hv; hv.x = h0; hv.y = h1;
                __nv_bfloat162 lv; lv.x = l0; lv.y = l1;
                *(__nv_bfloat162*)&g_yh[o] = hv;
                *(__nv_bfloat162*)&g_yl[o] = lv;
            }
}

// scores: S[b] = max_f Yf Yf^T (symmetric: 36 upper tiles + mirror). per b: M=N=1024, K=512
__global__ __launch_bounds__(256) void k_gemm_scores() {
    GEMM_SMEM();
    const int b = blockIdx.z;
    int t = blockIdx.x, bi = 0, rowlen = 8;
    while (t >= rowlen) { t -= rowlen; --rowlen; ++bi; }
    const int bj = bi + t;
    const int m0 = bi * BM, n0 = bj * BN;

    float best[4][4][4];
#pragma unroll
    for (int mt = 0; mt < 4; ++mt)
#pragma unroll
        for (int nt = 0; nt < 4; ++nt)
#pragma unroll
            for (int q = 0; q < 4; ++q) best[mt][nt][q] = -CUDART_INF_F;

    for (int f = 0; f < FF; ++f) {
        const __nv_bfloat16* Yh = g_yh + ((size_t)b * FF + f) * LL * HH;
        const __nv_bfloat16* Yl = g_yl + ((size_t)b * FF + f) * LL * HH;
        float acc[4][4][4] = {};
        gemm_main(acc, Yh, Yl, HH, Yh, Yl, HH, HH, m0, n0, sA0, sB0, sA1, sB1);
#pragma unroll
        for (int mt = 0; mt < 4; ++mt)
#pragma unroll
            for (int nt = 0; nt < 4; ++nt)
#pragma unroll
                for (int q = 0; q < 4; ++q)
                    best[mt][nt][q] = fmaxf(best[mt][nt][q], acc[mt][nt][q]);
    }

    float* Sb = g_S + (size_t)b * LL * LL;
    const int lane = threadIdx.x & 31, warp = threadIdx.x >> 5;
    const int wm = warp & 1, wn = warp >> 1;
    const int r = lane >> 2, c = (lane & 3) * 2;
#pragma unroll
    for (int mt = 0; mt < 4; ++mt)
#pragma unroll
        for (int nt = 0; nt < 4; ++nt)
#pragma unroll
            for (int half = 0; half < 2; ++half) {
                int m = m0 + wm * 64 + mt * 16 + r + half * 8;
                int n = n0 + wn * 32 + nt * 8 + c;
                float v0 = best[mt][nt][half * 2 + 0];
                float v1 = best[mt][nt][half * 2 + 1];
                float2 fv; fv.x = v0; fv.y = v1;
                *(float2*)&Sb[(size_t)m * LL + n] = fv;
                if (bi != bj) {
                    Sb[(size_t)n * LL + m] = v0;
                    Sb[(size_t)(n + 1) * LL + m] = v1;
                }
            }
}

// masked softmax (reference algebra), writes alpha hi/lo bf16
__global__ void k_softmax(const int* __restrict__ xmask) {
    const int row = blockIdx.x;
    const int b = row >> 10, l = row & 1023;
    const int t = threadIdx.x;
    const int* xb = xmask + b * LL;
    const float* Srow = g_S + (size_t)row * LL;
    const int ml = xb[l];

    float lm[4], msk[4];
    float mx = -CUDART_INF_F;
#pragma unroll
    for (int j = 0; j < 4; ++j) {
        int m = t + j * 256;
        float mk = (float)(ml * xb[m] * (m != l));
        float v = Srow[m] * mk;
        lm[j] = v; msk[j] = mk;
        mx = fmaxf(mx, v);
    }
    __shared__ float sh[256];
    sh[t] = mx; __syncthreads();
    for (int s = 128; s > 0; s >>= 1) {
        if (t < s) sh[t] = fmaxf(sh[t], sh[t + s]);
        __syncthreads();
    }
    const float rowmax = sh[0];
    __syncthreads();

    float e[4], z = 0.f, sm = 0.f;
#pragma unroll
    for (int j = 0; j < 4; ++j) {
        e[j] = expf(lm[j] - rowmax);
        z += e[j];
        sm += e[j] * msk[j];
    }
    sh[t] = z; __syncthreads();
    for (int s = 128; s > 0; s >>= 1) {
        if (t < s) sh[t] += sh[t + s];
        __syncthreads();
    }
    const float Z = sh[0];
    __syncthreads();
    sh[t] = sm; __syncthreads();
    for (int s = 128; s > 0; s >>= 1) {
        if (t < s) sh[t] += sh[t + s];
        __syncthreads();
    }
    const float SM = sh[0];

    const float inv = 1.0f / (SM + 1e-13f * Z);
#pragma unroll
    for (int j = 0; j < 4; ++j) {
        int m = t + j * 256;
        float a = e[j] * msk[j] * inv;
        __nv_bfloat16 hh, ll; split2(a, hh, ll);
        size_t o = (size_t)row * LL + m;
        g_ah[o] = hh; g_al[o] = ll;
    }
}

// enc: joint[:, H:2H] = alpha @ x_b.  per b: M=1024, N=512, K=1024
__global__ __launch_bounds__(256) void k_gemm_enc() {
    GEMM_SMEM();
    const int b = blockIdx.z;
    const int m0 = blockIdx.y * BM, n0 = blockIdx.x * BN;
    float acc[4][4][4] = {};
    gemm_main(acc, g_ah + (size_t)b * LL * LL, g_al + (size_t)b * LL * LL, LL,
              g_xth + (size_t)b * HH * LL, g_xtl + (size_t)b * HH * LL, LL,
              LL, m0, n0, sA0, sB0, sA1, sB1);

    const int lane = threadIdx.x & 31, warp = threadIdx.x >> 5;
    const int wm = warp & 1, wn = warp >> 1;
    const int r = lane >> 2, c = (lane & 3) * 2;
#pragma unroll
    for (int mt = 0; mt < 4; ++mt)
#pragma unroll
        for (int nt = 0; nt < 4; ++nt)
#pragma unroll
            for (int half = 0; half < 2; ++half) {
                int m = m0 + wm * 64 + mt * 16 + r + half * 8;
                int n = n0 + wn * 32 + nt * 8 + c;
                float v0 = acc[mt][nt][half * 2 + 0];
                float v1 = acc[mt][nt][half * 2 + 1];
                size_t o = ((size_t)b * LL + m) * H2 + HH + n;
                float2 fv; fv.x = v0; fv.y = v1;
                *(float2*)&g_joint[o] = fv;
                __nv_bfloat16 h0, l0, h1, l1;
                split2(v0, h0, l0); split2(v1, h1, l1);
                __nv_bfloat162 hv; hv.x = h0; hv.y = h1;
                __nv_bfloat162 lv; lv.x = l0; lv.y = l1;
                *(__nv_bfloat162*)&g_jh[o] = hv;
                *(__nv_bfloat162*)&g_jl[o] = lv;
            }
}

// gate: out = sigmoid(joint @ Wg + bg) * joint.  M=8192, N=1024, K=1024
__global__ __launch_bounds__(256) void k_gemm_gate(const float* __restrict__ bg,
                                                   float* __restrict__ out) {
    GEMM_SMEM();
    const int m0 = blockIdx.y * BM, n0 = blockIdx.x * BN;
    float acc[4][4][4] = {};
    gemm_main(acc, g_jh, g_jl, H2, g_wgh, g_wgl, H2, H2, m0, n0, sA0, sB0, sA1, sB1);

    const int lane = threadIdx.x & 31, warp = threadIdx.x >> 5;
    const int wm = warp & 1, wn = warp >> 1;
    const int r = lane >> 2, c = (lane & 3) * 2;
#pragma unroll
    for (int mt = 0; mt < 4; ++mt)
#pragma unroll
        for (int nt = 0; nt < 4; ++nt)
#pragma unroll
            for (int half = 0; half < 2; ++half) {
                int m = m0 + wm * 64 + mt * 16 + r + half * 8;
                int n = n0 + wn * 32 + nt * 8 + c;
                float2 bb = *(const float2*)&bg[n];
                float p0 = acc[mt][nt][half * 2 + 0] + bb.x;
                float p1 = acc[mt][nt][half * 2 + 1] + bb.y;
                float g0 = 1.0f / (1.0f + expf(-p0));
                float g1 = 1.0f / (1.0f + expf(-p1));
                size_t o = (size_t)m * H2 + n;
                float2 jv = *(const float2*)&g_joint[o];
                float2 ov; ov.x = g0 * jv.x; ov.y = g1 * jv.y;
                *(float2*)&out[o] = ov;
            }
}

// ---------------- launch ----------------------------------------------------
extern "C" void kernel_launch(void* const* d_in, const int* in_sizes, int n_in,
                              void* d_out, int out_size) {
    const float* x  = (const float*)d_in[0];
    const int*   xm = (const int*)d_in[1];
    const float* Wp = (const float*)d_in[2];
    const float* bp = (const float*)d_in[3];
    const float* Wg = (const float*)d_in[4];
    const float* bg = (const float*)d_in[5];
    float* out = (float*)d_out;

    dim3 tpre(32, 8);
    k_prep_x <<<dim3(HH / 32, LL / 32, BB), tpre>>>(x);
    k_prep_wp<<<dim3(HF / 32, HH / 32), tpre>>>(Wp, bp);
    k_prep_wg<<<dim3(H2 / 32, H2 / 32), tpre>>>(Wg);

    k_gemm_proj  <<<dim3(HF / BN, MROWS / BM), 256>>>();
    k_gemm_scores<<<dim3(36, 1, BB), 256>>>();
    k_softmax    <<<MROWS, 256>>>(xm);
    k_gemm_enc   <<<dim3(HH / BN, LL / BM, BB), 256>>>();
    k_gemm_gate  <<<dim3(H2 / BN, MROWS / BM), 256>>>(bg, out);
}

// round 4
// speedup vs baseline: 3.0301x; 1.2489x over previous
#include <cuda_runtime.h>
#include <cuda_bf16.h>
#include <math_constants.h>
#include <cstdint>

// Shapes (fixed)
#define BB 8
#define LL 1024
#define HH 512
#define FF 4
#define HF 2048
#define H2 1024
#define MROWS 8192

// ---------------- scratch (device globals) ----------------------------------
__device__ __align__(256) float g_S[(size_t)BB * LL * LL];
__device__ __align__(256) float g_joint[(size_t)MROWS * H2];
__device__ __align__(256) __nv_bfloat16 g_jh[(size_t)MROWS * H2];
__device__ __align__(256) __nv_bfloat16 g_jl[(size_t)MROWS * H2];
__device__ __align__(256) __nv_bfloat16 g_xth[(size_t)BB * HH * LL];
__device__ __align__(256) __nv_bfloat16 g_xtl[(size_t)BB * HH * LL];
__device__ __align__(256) __nv_bfloat16 g_wph[(size_t)HF * HH];
__device__ __align__(256) __nv_bfloat16 g_wpl[(size_t)HF * HH];
__device__ __align__(256) float g_bpr[HF];
__device__ __align__(256) __nv_bfloat16 g_wgh[(size_t)H2 * H2];
__device__ __align__(256) __nv_bfloat16 g_wgl[(size_t)H2 * H2];
__device__ __align__(256) __nv_bfloat16 g_yh[(size_t)BB * FF * LL * HH];
__device__ __align__(256) __nv_bfloat16 g_yl[(size_t)BB * FF * LL * HH];
__device__ __align__(256) __nv_bfloat16 g_ah[(size_t)BB * LL * LL];
__device__ __align__(256) __nv_bfloat16 g_al[(size_t)BB * LL * LL];

// ---------------- helpers ----------------------------------------------------
__device__ __forceinline__ void split2(float v, __nv_bfloat16& h, __nv_bfloat16& l) {
    h = __float2bfloat16_rn(v);
    l = __float2bfloat16_rn(v - __bfloat162float(h));
}
__device__ __forceinline__ void cp16(void* smem, const void* gmem) {
    unsigned s = (unsigned)__cvta_generic_to_shared(smem);
    asm volatile("cp.async.cg.shared.global [%0], [%1], 16;\n" :: "r"(s), "l"(gmem));
}
__device__ __forceinline__ void cp_commit() { asm volatile("cp.async.commit_group;\n"); }
__device__ __forceinline__ void cp_wait0()  { asm volatile("cp.async.wait_group 0;\n"); }

__device__ __forceinline__ void ldsm4(unsigned& r0, unsigned& r1, unsigned& r2, unsigned& r3,
                                      const void* p) {
    unsigned s = (unsigned)__cvta_generic_to_shared(p);
    asm volatile("ldmatrix.sync.aligned.m8n8.x4.shared.b16 {%0,%1,%2,%3}, [%4];\n"
                 : "=r"(r0), "=r"(r1), "=r"(r2), "=r"(r3) : "r"(s));
}
__device__ __forceinline__ void mma16816(float* c, const unsigned* a, const unsigned* b) {
    asm volatile(
        "mma.sync.aligned.m16n8k16.row.col.f32.bf16.bf16.f32 "
        "{%0,%1,%2,%3}, {%4,%5,%6,%7}, {%8,%9}, {%0,%1,%2,%3};\n"
        : "+f"(c[0]), "+f"(c[1]), "+f"(c[2]), "+f"(c[3])
        : "r"(a[0]), "r"(a[1]), "r"(a[2]), "r"(a[3]), "r"(b[0]), "r"(b[1]));
}

// ---------------- folded-split mma GEMM core ---------------------------------
// Block tile 128x128, K-tile 32, 256 threads (8 warps: 2m x 4n), warp tile 64x32.
// Per stage smem holds Ah, Al, Bh, Bl (each 128x32), double-buffered = 80KB dyn.
#define BM 128
#define BN 128
#define BK 32
#define SSTR 40
#define TILE_E (128 * SSTR)             // 5120 bf16 per tile buffer
#define STAGE_E (4 * TILE_E)            // Ah, Al, Bh, Bl
#define SMEM_BYTES (2 * STAGE_E * 2)    // 81920 bytes

__device__ __forceinline__ void load_stage(__nv_bfloat16* st,
                                           const __nv_bfloat16* Ah, const __nv_bfloat16* Al, int lda,
                                           const __nv_bfloat16* Bh, const __nv_bfloat16* Bl, int ldb,
                                           int m0, int n0, int kk, int tid) {
    __nv_bfloat16* sAH = st;
    __nv_bfloat16* sAL = st + TILE_E;
    __nv_bfloat16* sBH = st + 2 * TILE_E;
    __nv_bfloat16* sBL = st + 3 * TILE_E;
#pragma unroll
    for (int i = 0; i < 2; ++i) {
        int idx = tid + i * 256;
        int r = idx >> 2, c = (idx & 3) * 8;
        size_t ga = (size_t)(m0 + r) * lda + kk + c;
        size_t gb = (size_t)(n0 + r) * ldb + kk + c;
        cp16(&sAH[r * SSTR + c], &Ah[ga]);
        cp16(&sAL[r * SSTR + c], &Al[ga]);
        cp16(&sBH[r * SSTR + c], &Bh[gb]);
        cp16(&sBL[r * SSTR + c], &Bl[gb]);
    }
    cp_commit();
}

__device__ __forceinline__ void compute_stage(float (&acc)[4][4][4],
                                              const __nv_bfloat16* st,
                                              int wm, int wn, int lane) {
    const __nv_bfloat16* sAH = st;
    const __nv_bfloat16* sAL = st + TILE_E;
    const __nv_bfloat16* sBH = st + 2 * TILE_E;
    const __nv_bfloat16* sBL = st + 3 * TILE_E;
#pragma unroll
    for (int ks = 0; ks < 2; ++ks) {
        const int col = ks * 16 + (lane >> 4) * 8;
        const int arow = wm * 64 + (lane & 15);
        const int brow = wn * 32 + (lane & 15);
        unsigned a[4][4], bh[4][2], bl[4][2];
#pragma unroll
        for (int mt = 0; mt < 4; ++mt)
            ldsm4(a[mt][0], a[mt][1], a[mt][2], a[mt][3], &sAH[(arow + mt * 16) * SSTR + col]);
#pragma unroll
        for (int np = 0; np < 2; ++np) {
            unsigned r0, r1, r2, r3;
            ldsm4(r0, r1, r2, r3, &sBH[(brow + np * 16) * SSTR + col]);
            bh[np * 2 + 0][0] = r0; bh[np * 2 + 1][0] = r1;
            bh[np * 2 + 0][1] = r2; bh[np * 2 + 1][1] = r3;
            ldsm4(r0, r1, r2, r3, &sBL[(brow + np * 16) * SSTR + col]);
            bl[np * 2 + 0][0] = r0; bl[np * 2 + 1][0] = r1;
            bl[np * 2 + 0][1] = r2; bl[np * 2 + 1][1] = r3;
        }
#pragma unroll
        for (int mt = 0; mt < 4; ++mt)
#pragma unroll
            for (int nt = 0; nt < 4; ++nt) {
                mma16816(acc[mt][nt], a[mt], bh[nt]);
                mma16816(acc[mt][nt], a[mt], bl[nt]);
            }
#pragma unroll
        for (int mt = 0; mt < 4; ++mt)
            ldsm4(a[mt][0], a[mt][1], a[mt][2], a[mt][3], &sAL[(arow + mt * 16) * SSTR + col]);
#pragma unroll
        for (int mt = 0; mt < 4; ++mt)
#pragma unroll
            for (int nt = 0; nt < 4; ++nt)
                mma16816(acc[mt][nt], a[mt], bh[nt]);
    }
}

__device__ __forceinline__ void gemm_main(float (&acc)[4][4][4], __nv_bfloat16* sm,
                                          const __nv_bfloat16* Ah, const __nv_bfloat16* Al, int lda,
                                          const __nv_bfloat16* Bh, const __nv_bfloat16* Bl, int ldb,
                                          int K, int m0, int n0) {
    const int tid = threadIdx.x;
    const int lane = tid & 31, warp = tid >> 5;
    const int wm = warp & 1, wn = warp >> 1;
    const int S = K / BK;

    load_stage(sm, Ah, Al, lda, Bh, Bl, ldb, m0, n0, 0, tid);
    for (int s = 0; s < S; ++s) {
        cp_wait0();
        __syncthreads();
        if (s + 1 < S)
            load_stage(sm + ((s + 1) & 1) * STAGE_E, Ah, Al, lda, Bh, Bl, ldb,
                       m0, n0, (s + 1) * BK, tid);
        compute_stage(acc, sm + (s & 1) * STAGE_E, wm, wn, lane);
        __syncthreads();
    }
}

// ---------------- prep kernels -----------------------------------------------
__global__ void k_prep_x(const float* __restrict__ X) {
    __shared__ float tile[32][33];
    const int b = blockIdx.z;
    const int l0 = blockIdx.y * 32, h0 = blockIdx.x * 32;
    const int tx = threadIdx.x, ty = threadIdx.y;
#pragma unroll
    for (int i = 0; i < 4; ++i) {
        int l = l0 + ty + 8 * i;
        float v = X[((size_t)b * LL + l) * HH + h0 + tx];
        tile[ty + 8 * i][tx] = v;
        size_t jo = ((size_t)b * LL + l) * H2 + h0 + tx;
        g_joint[jo] = v;
        __nv_bfloat16 hh, ll; split2(v, hh, ll);
        g_jh[jo] = hh; g_jl[jo] = ll;
    }
    __syncthreads();
#pragma unroll
    for (int i = 0; i < 4; ++i) {
        int h = h0 + ty + 8 * i;
        float v = tile[tx][ty + 8 * i];
        size_t o = ((size_t)b * HH + h) * LL + l0 + tx;
        __nv_bfloat16 hh, ll; split2(v, hh, ll);
        g_xth[o] = hh; g_xtl[o] = ll;
    }
}

__global__ void k_prep_wp(const float* __restrict__ W, const float* __restrict__ bp) {
    __shared__ float tile[32][33];
    const int k0 = blockIdx.y * 32, n0 = blockIdx.x * 32;
    const int tx = threadIdx.x, ty = threadIdx.y;
#pragma unroll
    for (int i = 0; i < 4; ++i)
        tile[ty + 8 * i][tx] = W[(size_t)(k0 + ty + 8 * i) * HF + n0 + tx];
    __syncthreads();
#pragma unroll
    for (int i = 0; i < 4; ++i) {
        int n = n0 + ty + 8 * i;
        int np = ((n & 3) << 9) + (n >> 2);
        float v = tile[tx][ty + 8 * i];
        __nv_bfloat16 hh, ll; split2(v, hh, ll);
        size_t o = (size_t)np * HH + k0 + tx;
        g_wph[o] = hh; g_wpl[o] = ll;
        if (k0 == 0 && tx == 0) g_bpr[np] = bp[n];
    }
}

__global__ void k_prep_wg(const float* __restrict__ W) {
    __shared__ float tile[32][33];
    const int k0 = blockIdx.y * 32, n0 = blockIdx.x * 32;
    const int tx = threadIdx.x, ty = threadIdx.y;
#pragma unroll
    for (int i = 0; i < 4; ++i)
        tile[ty + 8 * i][tx] = W[(size_t)(k0 + ty + 8 * i) * H2 + n0 + tx];
    __syncthreads();
#pragma unroll
    for (int i = 0; i < 4; ++i) {
        int n = n0 + ty + 8 * i;
        float v = tile[tx][ty + 8 * i];
        __nv_bfloat16 hh, ll; split2(v, hh, ll);
        size_t o = (size_t)n * H2 + k0 + tx;
        g_wgh[o] = hh; g_wgl[o] = ll;
    }
}

// ---------------- GEMM kernels -------------------------------------------------
// proj: y = relu(x @ Wp + bp) -> yt hi/lo.  M=8192, N=2048(f-major), K=512
__global__ __launch_bounds__(256, 2) void k_gemm_proj() {
    extern __shared__ __nv_bfloat16 sm[];
    float acc[4][4][4] = {};
    const int m0 = blockIdx.y * BM, n0 = blockIdx.x * BN;
    gemm_main(acc, sm, g_jh, g_jl, H2, g_wph, g_wpl, HH, HH, m0, n0);

    const int lane = threadIdx.x & 31, warp = threadIdx.x >> 5;
    const int wm = warp & 1, wn = warp >> 1;
    const int r = lane >> 2, c = (lane & 3) * 2;
#pragma unroll
    for (int mt = 0; mt < 4; ++mt)
#pragma unroll
        for (int nt = 0; nt < 4; ++nt)
#pragma unroll
            for (int half = 0; half < 2; ++half) {
                int m = m0 + wm * 64 + mt * 16 + r + half * 8;
                int n = n0 + wn * 32 + nt * 8 + c;
                float2 bb = *(const float2*)&g_bpr[n];
                float v0 = fmaxf(acc[mt][nt][half * 2 + 0] + bb.x, 0.f);
                float v1 = fmaxf(acc[mt][nt][half * 2 + 1] + bb.y, 0.f);
                int b = m >> 10, l = m & 1023;
                int f = n >> 9, h = n & 511;
                size_t o = (((size_t)(b * FF + f)) * LL + l) * HH + h;
                __nv_bfloat16 h0, l0, h1, l1;
                split2(v0, h0, l0); split2(v1, h1, l1);
                __nv_bfloat162 hv; hv.x = h0; hv.y = h1;
                __nv_bfloat162 lv; lv.x = l0; lv.y = l1;
                *(__nv_bfloat162*)&g_yh[o] = hv;
                *(__nv_bfloat162*)&g_yl[o] = lv;
            }
}

// scores: S[b] = max_f Yf Yf^T, symmetric (36 upper tiles + mirror). per b: M=N=1024,K=512
__global__ __launch_bounds__(256, 2) void k_gemm_scores() {
    extern __shared__ __nv_bfloat16 sm[];
    const int b = blockIdx.z;
    int t = blockIdx.x, bi = 0, rowlen = 8;
    while (t >= rowlen) { t -= rowlen; --rowlen; ++bi; }
    const int bj = bi + t;
    const int m0 = bi * BM, n0 = bj * BN;

    float best[4][4][4];
#pragma unroll
    for (int mt = 0; mt < 4; ++mt)
#pragma unroll
        for (int nt = 0; nt < 4; ++nt)
#pragma unroll
            for (int q = 0; q < 4; ++q) best[mt][nt][q] = -CUDART_INF_F;

    for (int f = 0; f < FF; ++f) {
        const __nv_bfloat16* Yh = g_yh + ((size_t)(b * FF + f)) * LL * HH;
        const __nv_bfloat16* Yl = g_yl + ((size_t)(b * FF + f)) * LL * HH;
        float acc[4][4][4] = {};
        gemm_main(acc, sm, Yh, Yl, HH, Yh, Yl, HH, HH, m0, n0);
#pragma unroll
        for (int mt = 0; mt < 4; ++mt)
#pragma unroll
            for (int nt = 0; nt < 4; ++nt)
#pragma unroll
                for (int q = 0; q < 4; ++q)
                    best[mt][nt][q] = fmaxf(best[mt][nt][q], acc[mt][nt][q]);
    }

    float* Sb = g_S + (size_t)b * LL * LL;
    const int lane = threadIdx.x & 31, warp = threadIdx.x >> 5;
    const int wm = warp & 1, wn = warp >> 1;
    const int r = lane >> 2, c = (lane & 3) * 2;
#pragma unroll
    for (int mt = 0; mt < 4; ++mt)
#pragma unroll
        for (int nt = 0; nt < 4; ++nt)
#pragma unroll
            for (int half = 0; half < 2; ++half) {
                int m = m0 + wm * 64 + mt * 16 + r + half * 8;
                int n = n0 + wn * 32 + nt * 8 + c;
                float v0 = best[mt][nt][half * 2 + 0];
                float v1 = best[mt][nt][half * 2 + 1];
                float2 fv; fv.x = v0; fv.y = v1;
                *(float2*)&Sb[(size_t)m * LL + n] = fv;
                if (bi != bj) {
                    Sb[(size_t)n * LL + m] = v0;
                    Sb[(size_t)(n + 1) * LL + m] = v1;
                }
            }
}

// masked softmax (reference algebra), writes alpha hi/lo bf16
__global__ void k_softmax(const int* __restrict__ xmask) {
    const int row = blockIdx.x;
    const int b = row >> 10, l = row & 1023;
    const int t = threadIdx.x;
    const int* xb = xmask + b * LL;
    const float* Srow = g_S + (size_t)row * LL;
    const int ml = xb[l];

    float lm[4], msk[4];
    float mx = -CUDART_INF_F;
#pragma unroll
    for (int j = 0; j < 4; ++j) {
        int m = t + j * 256;
        float mk = (float)(ml * xb[m] * (m != l));
        float v = Srow[m] * mk;
        lm[j] = v; msk[j] = mk;
        mx = fmaxf(mx, v);
    }
    __shared__ float sh[256];
    sh[t] = mx; __syncthreads();
    for (int s = 128; s > 0; s >>= 1) {
        if (t < s) sh[t] = fmaxf(sh[t], sh[t + s]);
        __syncthreads();
    }
    const float rowmax = sh[0];
    __syncthreads();

    float e[4], z = 0.f, smv = 0.f;
#pragma unroll
    for (int j = 0; j < 4; ++j) {
        e[j] = expf(lm[j] - rowmax);
        z += e[j];
        smv += e[j] * msk[j];
    }
    sh[t] = z; __syncthreads();
    for (int s = 128; s > 0; s >>= 1) {
        if (t < s) sh[t] += sh[t + s];
        __syncthreads();
    }
    const float Z = sh[0];
    __syncthreads();
    sh[t] = smv; __syncthreads();
    for (int s = 128; s > 0; s >>= 1) {
        if (t < s) sh[t] += sh[t + s];
        __syncthreads();
    }
    const float SM = sh[0];

    const float inv = 1.0f / (SM + 1e-13f * Z);
#pragma unroll
    for (int j = 0; j < 4; ++j) {
        int m = t + j * 256;
        float a = e[j] * msk[j] * inv;
        __nv_bfloat16 hh, ll; split2(a, hh, ll);
        size_t o = (size_t)row * LL + m;
        g_ah[o] = hh; g_al[o] = ll;
    }
}

// enc: joint[:, H:2H] = alpha @ x_b.  per b: M=1024, N=512, K=1024
__global__ __launch_bounds__(256, 2) void k_gemm_enc() {
    extern __shared__ __nv_bfloat16 sm[];
    const int b = blockIdx.z;
    const int m0 = blockIdx.y * BM, n0 = blockIdx.x * BN;
    float acc[4][4][4] = {};
    gemm_main(acc, sm, g_ah + (size_t)b * LL * LL, g_al + (size_t)b * LL * LL, LL,
              g_xth + (size_t)b * HH * LL, g_xtl + (size_t)b * HH * LL, LL, LL, m0, n0);

    const int lane = threadIdx.x & 31, warp = threadIdx.x >> 5;
    const int wm = warp & 1, wn = warp >> 1;
    const int r = lane >> 2, c = (lane & 3) * 2;
#pragma unroll
    for (int mt = 0; mt < 4; ++mt)
#pragma unroll
        for (int nt = 0; nt < 4; ++nt)
#pragma unroll
            for (int half = 0; half < 2; ++half) {
                int m = m0 + wm * 64 + mt * 16 + r + half * 8;
                int n = n0 + wn * 32 + nt * 8 + c;
                float v0 = acc[mt][nt][half * 2 + 0];
                float v1 = acc[mt][nt][half * 2 + 1];
                size_t o = ((size_t)b * LL + m) * H2 + HH + n;
                float2 fv; fv.x = v0; fv.y = v1;
                *(float2*)&g_joint[o] = fv;
                __nv_bfloat16 h0, l0, h1, l1;
                split2(v0, h0, l0); split2(v1, h1, l1);
                __nv_bfloat162 hv; hv.x = h0; hv.y = h1;
                __nv_bfloat162 lv; lv.x = l0; lv.y = l1;
                *(__nv_bfloat162*)&g_jh[o] = hv;
                *(__nv_bfloat162*)&g_jl[o] = lv;
            }
}

// gate: out = sigmoid(joint @ Wg + bg) * joint.  M=8192, N=1024, K=1024
__global__ __launch_bounds__(256, 2) void k_gemm_gate(const float* __restrict__ bg,
                                                      float* __restrict__ out) {
    extern __shared__ __nv_bfloat16 sm[];
    const int m0 = blockIdx.y * BM, n0 = blockIdx.x * BN;
    float acc[4][4][4] = {};
    gemm_main(acc, sm, g_jh, g_jl, H2, g_wgh, g_wgl, H2, H2, m0, n0);

    const int lane = threadIdx.x & 31, warp = threadIdx.x >> 5;
    const int wm = warp & 1, wn = warp >> 1;
    const int r = lane >> 2, c = (lane & 3) * 2;
#pragma unroll
    for (int mt = 0; mt < 4; ++mt)
#pragma unroll
        for (int nt = 0; nt < 4; ++nt)
#pragma unroll
            for (int half = 0; half < 2; ++half) {
                int m = m0 + wm * 64 + mt * 16 + r + half * 8;
                int n = n0 + wn * 32 + nt * 8 + c;
                float2 bb = *(const float2*)&bg[n];
                float p0 = acc[mt][nt][half * 2 + 0] + bb.x;
                float p1 = acc[mt][nt][half * 2 + 1] + bb.y;
                float g0 = 1.0f / (1.0f + expf(-p0));
                float g1 = 1.0f / (1.0f + expf(-p1));
                size_t o = (size_t)m * H2 + n;
                float2 jv = *(const float2*)&g_joint[o];
                float2 ov; ov.x = g0 * jv.x; ov.y = g1 * jv.y;
                *(float2*)&out[o] = ov;
            }
}

// ---------------- launch --------------------------------------------------------
extern "C" void kernel_launch(void* const* d_in, const int* in_sizes, int n_in,
                              void* d_out, int out_size) {
    const float* x  = (const float*)d_in[0];
    const int*   xm = (const int*)d_in[1];
    const float* Wp = (const float*)d_in[2];
    const float* bp = (const float*)d_in[3];
    const float* Wg = (const float*)d_in[4];
    const float* bg = (const float*)d_in[5];
    float* out = (float*)d_out;

    cudaFuncSetAttribute(k_gemm_proj,   cudaFuncAttributeMaxDynamicSharedMemorySize, SMEM_BYTES);
    cudaFuncSetAttribute(k_gemm_scores, cudaFuncAttributeMaxDynamicSharedMemorySize, SMEM_BYTES);
    cudaFuncSetAttribute(k_gemm_enc,    cudaFuncAttributeMaxDynamicSharedMemorySize, SMEM_BYTES);
    cudaFuncSetAttribute(k_gemm_gate,   cudaFuncAttributeMaxDynamicSharedMemorySize, SMEM_BYTES);

    dim3 tpre(32, 8);
    k_prep_x <<<dim3(HH / 32, LL / 32, BB), tpre>>>(x);
    k_prep_wp<<<dim3(HF / 32, HH / 32), tpre>>>(Wp, bp);
    k_prep_wg<<<dim3(H2 / 32, H2 / 32), tpre>>>(Wg);

    k_gemm_proj  <<<dim3(HF / BN, MROWS / BM), 256, SMEM_BYTES>>>();
    k_gemm_scores<<<dim3(36, 1, BB), 256, SMEM_BYTES>>>();
    k_softmax    <<<MROWS, 256>>>(xm);
    k_gemm_enc   <<<dim3(HH / BN, LL / BM, BB), 256, SMEM_BYTES>>>();
    k_gemm_gate  <<<dim3(H2 / BN, MROWS / BM), 256, SMEM_BYTES>>>(bg, out);
}